// round 13
// baseline (speedup 1.0000x reference)
#include <cuda_runtime.h>

// ---------------------------------------------------------------------------
// RecNet: xh = x@Wx^T + bx (once); 128x  h = relu(xh + h@Wh^T + bh);
// out = h@Wy^T + by.
//
// Multi-launch skeleton (validated R8). GEMM kernels upgraded to 256 thr/CTA
// (8 warps -> 2 per SMSP) for latency hiding; inner loop = 1 LDS.64 (A pair)
// + 2 LDS.128 (B duplicated pairs from smem) + 4 FFMA2 per k. Exact fp32.
// ---------------------------------------------------------------------------

#define GTHR 256   // threads for GEMM kernels
#define TTHR 128   // threads for transpose kernel

#define B_  512   // batch
#define H_  512   // hidden
#define DI_ 128   // input dim (= timestep count T)
#define DO_ 256   // output dim
#define TSTEPS 128

typedef unsigned long long ull;

// ---- device scratch (static: no allocations allowed) ----------------------
__device__ float g_WhT[H_ * H_];     // [k][j]
__device__ float g_WxT[DI_ * H_];    // [k][j]
__device__ float g_xT [DI_ * B_];    // [k][b]
__device__ float g_WyT[H_ * DO_];    // [k][j]
__device__ float g_xh [H_ * B_];     // xh^T : [j][b]
__device__ float g_hbuf[2][H_ * B_]; // h^T  : [j][b]  (ping-pong)

// packed fp32x2 fma (sm_100+)
#define FFMA2(d, a, b, c) \
    asm("fma.rn.f32x2 %0, %1, %2, %3;" : "=l"(d) : "l"(a), "l"(b), "l"(c))
#define PACK2(d, lo, hi) \
    asm("mov.b64 %0, {%1, %2};" : "=l"(d) : "f"(lo), "f"(hi))
#define UNPACK2(lo, hi, s) \
    asm("mov.b64 {%0, %1}, %2;" : "=f"(lo), "=f"(hi) : "l"(s))

// ---- 32x32 tile transpose: src[R][C] row-major -> dst[C][R] ----------------
__device__ __forceinline__ void transpose_job(const float* __restrict__ src,
                                              float* __restrict__ dst,
                                              int R, int C, float* s)
{
    const int TR = R >> 5, TC = C >> 5;
    const int nt = TR * TC;
    const int tid = threadIdx.x;
    const int lr = tid >> 5, lc = tid & 31;
    for (int t = blockIdx.x; t < nt; t += (int)gridDim.x) {
        const int tr = t / TC, tc = t % TC;
        __syncthreads();
#pragma unroll
        for (int i = 0; i < 8; i++) {
            int r = lr + 4 * i;
            s[r * 33 + lc] = src[(tr * 32 + r) * C + tc * 32 + lc];
        }
        __syncthreads();
#pragma unroll
        for (int i = 0; i < 8; i++) {
            int r = lr + 4 * i;
            dst[(tc * 32 + r) * R + tr * 32 + lc] = s[lc * 33 + r];
        }
    }
}

__global__ void __launch_bounds__(TTHR, 1) transpose_kernel(
    const float* __restrict__ x,  const float* __restrict__ Wx,
    const float* __restrict__ Wh, const float* __restrict__ Wy)
{
    __shared__ float s[32 * 33];
    transpose_job(Wh, g_WhT, H_,  H_,  s);   // [512,512] -> [k][j]
    transpose_job(Wx, g_WxT, H_,  DI_, s);   // [512,128] -> [128][512]
    transpose_job(x,  g_xT,  B_,  DI_, s);   // [512,128] -> [128][512]
    transpose_job(Wy, g_WyT, DO_, H_,  s);   // [256,512] -> [512][256]
}

// ---- 64x32 tile GEMM, 256 threads ------------------------------------------
// Thread map: tm = tid&31 (m pair 2tm,2tm+1), tn = tid>>5 (n group 4tn..+3).
// acc[j] = packed (C[2tm][n0+4tn+j], C[2tm+1][n0+4tn+j]).
// sA: [k][m] stride 68.  sBd: [k][dup n] stride 72 — value B[n] at floats
// 2(n-n0), 2(n-n0)+1, so thread reads 2x ld.shared.v2.b64 (warp-broadcast).
__device__ __forceinline__ void gemm_tile(const float* __restrict__ A,
                                          const float* __restrict__ Bm,
                                          int ldb, int nkt, int m0, int n0,
                                          float clo[4], float chi[4])
{
    __shared__ float sA [32 * 68];
    __shared__ float sBd[32 * 72];

    const int tid = threadIdx.x;
    const int tm = tid & 31, tn = tid >> 5;

    ull acc[4];
    {
        ull z; PACK2(z, 0.f, 0.f);
#pragma unroll
        for (int j = 0; j < 4; j++) acc[j] = z;
    }

    float4 pa[2], pb;
    // prefetch K-tile 0
#pragma unroll
    for (int i = 0; i < 2; i++) {
        int idx = tid + i * GTHR; int kk = idx >> 4, cc = idx & 15;
        pa[i] = *(const float4*)&A[kk * B_ + m0 + 4 * cc];
    }
    {
        int kk = tid >> 3, cc = tid & 7;
        pb = *(const float4*)&Bm[kk * ldb + n0 + 4 * cc];
    }

    const unsigned aAddr = (unsigned)__cvta_generic_to_shared(sA)  + 8 * tm;
    const unsigned bAddr = (unsigned)__cvta_generic_to_shared(sBd) + 32 * tn;

    for (int kt = 0; kt < nkt; kt++) {
        __syncthreads();   // previous tile fully consumed
#pragma unroll
        for (int i = 0; i < 2; i++) {
            int idx = tid + i * GTHR; int kk = idx >> 4, cc = idx & 15;
            *(float4*)&sA[kk * 68 + 4 * cc] = pa[i];
        }
        {
            int kk = tid >> 3, cc = tid & 7;
            *(float4*)&sBd[kk * 72 + 8 * cc]     = make_float4(pb.x, pb.x, pb.y, pb.y);
            *(float4*)&sBd[kk * 72 + 8 * cc + 4] = make_float4(pb.z, pb.z, pb.w, pb.w);
        }
        __syncthreads();
        if (kt + 1 < nkt) {  // prefetch next tile under compute
            const float* An = A  + (kt + 1) * 32 * B_;
            const float* Bn = Bm + (kt + 1) * 32 * ldb;
#pragma unroll
            for (int i = 0; i < 2; i++) {
                int idx = tid + i * GTHR; int kk = idx >> 4, cc = idx & 15;
                pa[i] = *(const float4*)&An[kk * B_ + m0 + 4 * cc];
            }
            {
                int kk = tid >> 3, cc = tid & 7;
                pb = *(const float4*)&Bn[kk * ldb + n0 + 4 * cc];
            }
        }
#pragma unroll
        for (int k = 0; k < 32; k++) {
            ull a01, b0, b1, b2, b3;
            asm("ld.shared.b64 %0, [%1];"
                : "=l"(a01) : "r"(aAddr + k * 272));
            asm("ld.shared.v2.b64 {%0,%1}, [%2];"
                : "=l"(b0), "=l"(b1) : "r"(bAddr + k * 288));
            asm("ld.shared.v2.b64 {%0,%1}, [%2];"
                : "=l"(b2), "=l"(b3) : "r"(bAddr + k * 288 + 16));
            FFMA2(acc[0], a01, b0, acc[0]);
            FFMA2(acc[1], a01, b1, acc[1]);
            FFMA2(acc[2], a01, b2, acc[2]);
            FFMA2(acc[3], a01, b3, acc[3]);
        }
    }

#pragma unroll
    for (int j = 0; j < 4; j++) UNPACK2(clo[j], chi[j], acc[j]);
}

// ---- phase A: xh^T = (x @ Wx^T + bx)^T ; h1 = relu(xh + bh) ----------------
__global__ void __launch_bounds__(GTHR, 1) phaseA_kernel(
    const float* __restrict__ bx, const float* __restrict__ bh)
{
    float clo[4], chi[4];
    const int cta = blockIdx.x;
    const int m0 = (cta & 7) * 64, n0 = (cta >> 3) * 32;
    gemm_tile(g_xT, g_WxT, H_, DI_ / 32, m0, n0, clo, chi);

    const int tid = threadIdx.x;
    const int gm = m0 + 2 * (tid & 31);
    const int tn = tid >> 5;
#pragma unroll
    for (int j = 0; j < 4; j++) {
        int n = n0 + 4 * tn + j;
        float bxv = bx[n], bhv = bh[n];
        float2 v, h;
        v.x = clo[j] + bxv; v.y = chi[j] + bxv;
        *(float2*)&g_xh[n * B_ + gm] = v;
        h.x = fmaxf(v.x + bhv, 0.f); h.y = fmaxf(v.y + bhv, 0.f);
        *(float2*)&g_hbuf[0][n * B_ + gm] = h;
    }
}

// ---- one recurrent step: hbuf[cur^1] = relu(xh + hbuf[cur]@Wh^T + bh) ------
__global__ void __launch_bounds__(GTHR, 1) step_kernel(
    int cur, const float* __restrict__ bh)
{
    float clo[4], chi[4];
    const int cta = blockIdx.x;
    const int m0 = (cta & 7) * 64, n0 = (cta >> 3) * 32;
    gemm_tile(g_hbuf[cur], g_WhT, H_, H_ / 32, m0, n0, clo, chi);

    const int tid = threadIdx.x;
    const int gm = m0 + 2 * (tid & 31);
    const int tn = tid >> 5;
    float* __restrict__ dst = g_hbuf[cur ^ 1];
#pragma unroll
    for (int j = 0; j < 4; j++) {
        int n = n0 + 4 * tn + j;
        float bhv = bh[n];
        float2 xv = *(const float2*)&g_xh[n * B_ + gm];
        float2 h;
        h.x = fmaxf(clo[j] + xv.x + bhv, 0.f);
        h.y = fmaxf(chi[j] + xv.y + bhv, 0.f);
        *(float2*)&dst[n * B_ + gm] = h;
    }
}

// ---- output: out = h_final @ Wy^T + by  (h_final in g_hbuf[1]) -------------
__global__ void __launch_bounds__(GTHR, 1) out_kernel(
    const float* __restrict__ by, float* __restrict__ out)
{
    float clo[4], chi[4];
    const int cta = blockIdx.x;                 // 64 CTAs: 8 m x 8 n tiles
    const int m0 = (cta & 7) * 64, n0 = (cta >> 3) * 32;
    gemm_tile(g_hbuf[(TSTEPS - 1) & 1], g_WyT, DO_, H_ / 32, m0, n0, clo, chi);

    const int tid = threadIdx.x;
    const int gm = m0 + 2 * (tid & 31);
    const int gn = n0 + 4 * (tid >> 5);
    float b0 = by[gn], b1 = by[gn + 1], b2 = by[gn + 2], b3 = by[gn + 3];
    float4 olo, ohi;
    olo.x = clo[0] + b0; olo.y = clo[1] + b1; olo.z = clo[2] + b2; olo.w = clo[3] + b3;
    ohi.x = chi[0] + b0; ohi.y = chi[1] + b1; ohi.z = chi[2] + b2; ohi.w = chi[3] + b3;
    *(float4*)&out[(gm + 0) * DO_ + gn] = olo;
    *(float4*)&out[(gm + 1) * DO_ + gn] = ohi;
}

// ---------------------------------------------------------------------------
extern "C" void kernel_launch(void* const* d_in, const int* in_sizes, int n_in,
                              void* d_out, int out_size)
{
    const float* x  = (const float*)d_in[0];  // [512,128]
    const float* Wx = (const float*)d_in[1];  // [512,128]
    const float* bx = (const float*)d_in[2];  // [512]
    const float* Wh = (const float*)d_in[3];  // [512,512]
    const float* bh = (const float*)d_in[4];  // [512]
    const float* Wy = (const float*)d_in[5];  // [256,512]
    const float* by = (const float*)d_in[6];  // [256]
    float* out = (float*)d_out;               // [512,256]

    transpose_kernel<<<128, TTHR>>>(x, Wx, Wh, Wy);
    phaseA_kernel<<<128, GTHR>>>(bx, bh);              // h1 in g_hbuf[0]
    for (int t = 1; t < TSTEPS; t++)
        step_kernel<<<128, GTHR>>>((t - 1) & 1, bh);   // final h in g_hbuf[1]
    out_kernel<<<64, GTHR>>>(by, out);
}

// round 15
// speedup vs baseline: 1.1431x; 1.1431x over previous
#include <cuda_runtime.h>

// ---------------------------------------------------------------------------
// RecNet: xh = x@Wx^T + bx (once); 128x  h = relu(xh + h@Wh^T + bh);
// out = h@Wy^T + by.
//
// Multi-launch skeleton. GEMM: 256 thr/CTA (2 warps/SMSP), 64x32 tile,
// 4m x 2n per thread. All smem loads are compiler-visible C++ double2
// (packed fp32 pairs); only the FMA itself is asm (fma.rn.f32x2, rt2,
// validated R8/R13). B stored duplicated in smem so no register packing.
// ---------------------------------------------------------------------------

#define GTHR 256   // threads for GEMM kernels
#define TTHR 128   // threads for transpose kernel

#define B_  512   // batch
#define H_  512   // hidden
#define DI_ 128   // input dim (= timestep count T)
#define DO_ 256   // output dim
#define TSTEPS 128

typedef unsigned long long ull;

// ---- device scratch (static: no allocations allowed) ----------------------
__device__ float g_WhT[H_ * H_];     // [k][j]
__device__ float g_WxT[DI_ * H_];    // [k][j]
__device__ float g_xT [DI_ * B_];    // [k][b]
__device__ float g_WyT[H_ * DO_];    // [k][j]
__device__ float g_xh [H_ * B_];     // xh^T : [j][b]
__device__ float g_hbuf[2][H_ * B_]; // h^T  : [j][b]  (ping-pong)

// packed fp32x2 fma (sm_100+); d,a,b,c are b64 holding (f32 lo, f32 hi)
#define FFMA2(d, a, b, c) \
    asm("fma.rn.f32x2 %0, %1, %2, %3;" : "=l"(d) : "l"(a), "l"(b), "l"(c))
#define UNPACK2(lo, hi, s) \
    asm("mov.b64 {%0, %1}, %2;" : "=f"(lo), "=f"(hi) : "l"(s))

// ---- 32x32 tile transpose: src[R][C] row-major -> dst[C][R] ----------------
__device__ __forceinline__ void transpose_job(const float* __restrict__ src,
                                              float* __restrict__ dst,
                                              int R, int C, float* s)
{
    const int TR = R >> 5, TC = C >> 5;
    const int nt = TR * TC;
    const int tid = threadIdx.x;
    const int lr = tid >> 5, lc = tid & 31;
    for (int t = blockIdx.x; t < nt; t += (int)gridDim.x) {
        const int tr = t / TC, tc = t % TC;
        __syncthreads();
#pragma unroll
        for (int i = 0; i < 8; i++) {
            int r = lr + 4 * i;
            s[r * 33 + lc] = src[(tr * 32 + r) * C + tc * 32 + lc];
        }
        __syncthreads();
#pragma unroll
        for (int i = 0; i < 8; i++) {
            int r = lr + 4 * i;
            dst[(tc * 32 + r) * R + tr * 32 + lc] = s[lc * 33 + r];
        }
    }
}

__global__ void __launch_bounds__(TTHR, 1) transpose_kernel(
    const float* __restrict__ x,  const float* __restrict__ Wx,
    const float* __restrict__ Wh, const float* __restrict__ Wy)
{
    __shared__ float s[32 * 33];
    transpose_job(Wh, g_WhT, H_,  H_,  s);   // [512,512] -> [k][j]
    transpose_job(Wx, g_WxT, H_,  DI_, s);   // [512,128] -> [128][512]
    transpose_job(x,  g_xT,  B_,  DI_, s);   // [512,128] -> [128][512]
    transpose_job(Wy, g_WyT, DO_, H_,  s);   // [256,512] -> [512][256]
}

// ---- 64x32 tile GEMM, 256 threads, 4m x 2n per thread ----------------------
// tm = tid&15  -> m group m0+4tm..+3 (as two packed pairs)
// tn = tid>>4  -> n pair  n0+2tn, n0+2tn+1
// sA [k][m]   stride 68: packed m pairs read as double2 (16B, aligned).
// sBd[k][dup] stride 72: float 2j,2j+1 both = B[n0+j]; read as double2.
// cA = C[m0+4tm..+3][n0+2tn], cB = same for n0+2tn+1.
__device__ __forceinline__ void gemm_tile(const float* __restrict__ A,
                                          const float* __restrict__ Bm,
                                          int ldb, int nkt, int m0, int n0,
                                          float4& cA, float4& cB)
{
    __shared__ __align__(16) float sA [32 * 68];
    __shared__ __align__(16) float sBd[32 * 72];

    const int tid = threadIdx.x;
    const int tm = tid & 15, tn = tid >> 4;

    ull a00 = 0ull, a01 = 0ull, a10 = 0ull, a11 = 0ull;

    float4 pa[2], pb;
    // prefetch K-tile 0
#pragma unroll
    for (int i = 0; i < 2; i++) {
        int idx = tid + i * GTHR; int kk = idx >> 4, cc = idx & 15;
        pa[i] = *(const float4*)&A[kk * B_ + m0 + 4 * cc];
    }
    {
        int kk = tid >> 3, cc = tid & 7;
        pb = *(const float4*)&Bm[kk * ldb + n0 + 4 * cc];
    }

    for (int kt = 0; kt < nkt; kt++) {
        __syncthreads();   // previous tile fully consumed
#pragma unroll
        for (int i = 0; i < 2; i++) {
            int idx = tid + i * GTHR; int kk = idx >> 4, cc = idx & 15;
            *(float4*)&sA[kk * 68 + 4 * cc] = pa[i];
        }
        {
            int kk = tid >> 3, cc = tid & 7;
            *(float4*)&sBd[kk * 72 + 8 * cc]     = make_float4(pb.x, pb.x, pb.y, pb.y);
            *(float4*)&sBd[kk * 72 + 8 * cc + 4] = make_float4(pb.z, pb.z, pb.w, pb.w);
        }
        __syncthreads();
        if (kt + 1 < nkt) {  // prefetch next tile under compute
            const float* An = A  + (kt + 1) * 32 * B_;
            const float* Bn = Bm + (kt + 1) * 32 * ldb;
#pragma unroll
            for (int i = 0; i < 2; i++) {
                int idx = tid + i * GTHR; int kk = idx >> 4, cc = idx & 15;
                pa[i] = *(const float4*)&An[kk * B_ + m0 + 4 * cc];
            }
            {
                int kk = tid >> 3, cc = tid & 7;
                pb = *(const float4*)&Bn[kk * ldb + n0 + 4 * cc];
            }
        }
#pragma unroll
        for (int k = 0; k < 32; k++) {
            // compiler-visible smem loads (schedulable / pipelinable)
            double2 av = *(const double2*)&sA [k * 68 + 4 * tm];
            double2 bv = *(const double2*)&sBd[k * 72 + 4 * tn];
            ull am01 = __double_as_longlong(av.x);  // m 4tm, 4tm+1
            ull am23 = __double_as_longlong(av.y);  // m 4tm+2, 4tm+3
            ull bnA  = __double_as_longlong(bv.x);  // dup B[n0+2tn]
            ull bnB  = __double_as_longlong(bv.y);  // dup B[n0+2tn+1]
            FFMA2(a00, am01, bnA, a00);
            FFMA2(a01, am01, bnB, a01);
            FFMA2(a10, am23, bnA, a10);
            FFMA2(a11, am23, bnB, a11);
        }
    }

    UNPACK2(cA.x, cA.y, a00);
    UNPACK2(cA.z, cA.w, a10);
    UNPACK2(cB.x, cB.y, a01);
    UNPACK2(cB.z, cB.w, a11);
}

// ---- phase A: xh^T = (x @ Wx^T + bx)^T ; h1 = relu(xh + bh) ----------------
__global__ void __launch_bounds__(GTHR, 1) phaseA_kernel(
    const float* __restrict__ bx, const float* __restrict__ bh)
{
    float4 cA, cB;
    const int cta = blockIdx.x;
    const int m0 = (cta & 7) * 64, n0 = (cta >> 3) * 32;
    gemm_tile(g_xT, g_WxT, H_, DI_ / 32, m0, n0, cA, cB);

    const int tid = threadIdx.x;
    const int gm = m0 + 4 * (tid & 15);
    const int nA = n0 + 2 * (tid >> 4);

#pragma unroll
    for (int e = 0; e < 2; e++) {
        int n = nA + e;
        float4 c = e ? cB : cA;
        float bxv = bx[n], bhv = bh[n];
        float4 v, h;
        v.x = c.x + bxv; v.y = c.y + bxv; v.z = c.z + bxv; v.w = c.w + bxv;
        *(float4*)&g_xh[n * B_ + gm] = v;
        h.x = fmaxf(v.x + bhv, 0.f); h.y = fmaxf(v.y + bhv, 0.f);
        h.z = fmaxf(v.z + bhv, 0.f); h.w = fmaxf(v.w + bhv, 0.f);
        *(float4*)&g_hbuf[0][n * B_ + gm] = h;
    }
}

// ---- one recurrent step: hbuf[cur^1] = relu(xh + hbuf[cur]@Wh^T + bh) ------
__global__ void __launch_bounds__(GTHR, 1) step_kernel(
    int cur, const float* __restrict__ bh)
{
    float4 cA, cB;
    const int cta = blockIdx.x;
    const int m0 = (cta & 7) * 64, n0 = (cta >> 3) * 32;
    gemm_tile(g_hbuf[cur], g_WhT, H_, H_ / 32, m0, n0, cA, cB);

    const int tid = threadIdx.x;
    const int gm = m0 + 4 * (tid & 15);
    const int nA = n0 + 2 * (tid >> 4);
    float* __restrict__ dst = g_hbuf[cur ^ 1];

#pragma unroll
    for (int e = 0; e < 2; e++) {
        int n = nA + e;
        float4 c = e ? cB : cA;
        float bhv = bh[n];
        float4 xv = *(const float4*)&g_xh[n * B_ + gm];
        float4 h;
        h.x = fmaxf(c.x + xv.x + bhv, 0.f);
        h.y = fmaxf(c.y + xv.y + bhv, 0.f);
        h.z = fmaxf(c.z + xv.z + bhv, 0.f);
        h.w = fmaxf(c.w + xv.w + bhv, 0.f);
        *(float4*)&dst[n * B_ + gm] = h;
    }
}

// ---- output: out = h_final @ Wy^T + by  (h_final in g_hbuf[1]) -------------
__global__ void __launch_bounds__(GTHR, 1) out_kernel(
    const float* __restrict__ by, float* __restrict__ out)
{
    float4 cA, cB;
    const int cta = blockIdx.x;                 // 64 CTAs: 8 m x 8 n tiles
    const int m0 = (cta & 7) * 64, n0 = (cta >> 3) * 32;
    gemm_tile(g_hbuf[(TSTEPS - 1) & 1], g_WyT, DO_, H_ / 32, m0, n0, cA, cB);

    const int tid = threadIdx.x;
    const int gm = m0 + 4 * (tid & 15);
    const int nA = n0 + 2 * (tid >> 4);
    float bA = by[nA], bB = by[nA + 1];

    // out is [b][o] row-major: per m row store 2 adjacent n values
    out[(gm + 0) * DO_ + nA]     = cA.x + bA;
    out[(gm + 0) * DO_ + nA + 1] = cB.x + bB;
    out[(gm + 1) * DO_ + nA]     = cA.y + bA;
    out[(gm + 1) * DO_ + nA + 1] = cB.y + bB;
    out[(gm + 2) * DO_ + nA]     = cA.z + bA;
    out[(gm + 2) * DO_ + nA + 1] = cB.z + bB;
    out[(gm + 3) * DO_ + nA]     = cA.w + bA;
    out[(gm + 3) * DO_ + nA + 1] = cB.w + bB;
}

// ---------------------------------------------------------------------------
extern "C" void kernel_launch(void* const* d_in, const int* in_sizes, int n_in,
                              void* d_out, int out_size)
{
    const float* x  = (const float*)d_in[0];  // [512,128]
    const float* Wx = (const float*)d_in[1];  // [512,128]
    const float* bx = (const float*)d_in[2];  // [512]
    const float* Wh = (const float*)d_in[3];  // [512,512]
    const float* bh = (const float*)d_in[4];  // [512]
    const float* Wy = (const float*)d_in[5];  // [256,512]
    const float* by = (const float*)d_in[6];  // [256]
    float* out = (float*)d_out;               // [512,256]

    transpose_kernel<<<128, TTHR>>>(x, Wx, Wh, Wy);
    phaseA_kernel<<<128, GTHR>>>(bx, bh);              // h1 in g_hbuf[0]
    for (int t = 1; t < TSTEPS; t++)
        step_kernel<<<128, GTHR>>>((t - 1) & 1, bh);   // final h in g_hbuf[1]
    out_kernel<<<64, GTHR>>>(by, out);
}

// round 16
// speedup vs baseline: 1.3674x; 1.1962x over previous
#include <cuda_runtime.h>

// ---------------------------------------------------------------------------
// RecNet: xh = x@Wx^T + bx (once); 128x  h = relu(xh + h@Wh^T + bh);
// out = h@Wy^T + by.
//
// Multi-launch skeleton (R8-validated). GEMM: 256 thr/CTA (2 warps/SMSP),
// 64x32 tile, 4m x 2n per thread, pure C++ scalar fmaf inner loop (the
// R8-measured-best loop shape; all FFMA2/asm variants measured slower).
// ---------------------------------------------------------------------------

#define GTHR 256   // threads for GEMM kernels
#define TTHR 128   // threads for transpose kernel

#define B_  512   // batch
#define H_  512   // hidden
#define DI_ 128   // input dim (= timestep count T)
#define DO_ 256   // output dim
#define TSTEPS 128

// ---- device scratch (static: no allocations allowed) ----------------------
__device__ float g_WhT[H_ * H_];     // [k][j]
__device__ float g_WxT[DI_ * H_];    // [k][j]
__device__ float g_xT [DI_ * B_];    // [k][b]
__device__ float g_WyT[H_ * DO_];    // [k][j]
__device__ float g_xh [H_ * B_];     // xh^T : [j][b]
__device__ float g_hbuf[2][H_ * B_]; // h^T  : [j][b]  (ping-pong)

// ---- 32x32 tile transpose: src[R][C] row-major -> dst[C][R] ----------------
__device__ __forceinline__ void transpose_job(const float* __restrict__ src,
                                              float* __restrict__ dst,
                                              int R, int C, float* s)
{
    const int TR = R >> 5, TC = C >> 5;
    const int nt = TR * TC;
    const int tid = threadIdx.x;
    const int lr = tid >> 5, lc = tid & 31;
    for (int t = blockIdx.x; t < nt; t += (int)gridDim.x) {
        const int tr = t / TC, tc = t % TC;
        __syncthreads();
#pragma unroll
        for (int i = 0; i < 8; i++) {
            int r = lr + 4 * i;
            s[r * 33 + lc] = src[(tr * 32 + r) * C + tc * 32 + lc];
        }
        __syncthreads();
#pragma unroll
        for (int i = 0; i < 8; i++) {
            int r = lr + 4 * i;
            dst[(tc * 32 + r) * R + tr * 32 + lc] = s[lc * 33 + r];
        }
    }
}

__global__ void __launch_bounds__(TTHR, 1) transpose_kernel(
    const float* __restrict__ x,  const float* __restrict__ Wx,
    const float* __restrict__ Wh, const float* __restrict__ Wy)
{
    __shared__ float s[32 * 33];
    transpose_job(Wh, g_WhT, H_,  H_,  s);   // [512,512] -> [k][j]
    transpose_job(Wx, g_WxT, H_,  DI_, s);   // [512,128] -> [128][512]
    transpose_job(x,  g_xT,  B_,  DI_, s);   // [512,128] -> [128][512]
    transpose_job(Wy, g_WyT, DO_, H_,  s);   // [256,512] -> [512][256]
}

// ---- 64x32 tile GEMM, 256 threads, 4m x 2n per thread ----------------------
// tm = tid&15  -> m rows m0+4tm .. +3   (float4 from sA)
// tn = tid>>4  -> n cols n0+2tn, +1     (float2 from sB)
// c0 = C[m rows][n0+2tn], c1 = C[m rows][n0+2tn+1]
__device__ __forceinline__ void gemm_tile(const float* __restrict__ A,
                                          const float* __restrict__ Bm,
                                          int ldb, int nkt, int m0, int n0,
                                          float4& c0, float4& c1)
{
    __shared__ __align__(16) float sA[32 * 68];   // 32 k x 64 m (+4 pad)
    __shared__ __align__(16) float sB[32 * 36];   // 32 k x 32 n (+4 pad)

    const int tid = threadIdx.x;
    const int tm = tid & 15, tn = tid >> 4;

    c0 = make_float4(0.f, 0.f, 0.f, 0.f);
    c1 = make_float4(0.f, 0.f, 0.f, 0.f);

    float4 pa[2], pb;
    // register prefetch of K-tile 0
#pragma unroll
    for (int i = 0; i < 2; i++) {
        int idx = tid + i * GTHR; int kk = idx >> 4, cc = idx & 15;
        pa[i] = *(const float4*)&A[kk * B_ + m0 + 4 * cc];
    }
    {
        int kk = tid >> 3, cc = tid & 7;   // 256 thr covers 32x8 float4 once
        pb = *(const float4*)&Bm[kk * ldb + n0 + 4 * cc];
    }

    for (int kt = 0; kt < nkt; kt++) {
        __syncthreads();   // previous tile fully consumed
#pragma unroll
        for (int i = 0; i < 2; i++) {
            int idx = tid + i * GTHR; int kk = idx >> 4, cc = idx & 15;
            *(float4*)&sA[kk * 68 + 4 * cc] = pa[i];
        }
        {
            int kk = tid >> 3, cc = tid & 7;
            *(float4*)&sB[kk * 36 + 4 * cc] = pb;
        }
        __syncthreads();
        if (kt + 1 < nkt) {  // prefetch next tile under compute
            const float* An = A  + (kt + 1) * 32 * B_;
            const float* Bn = Bm + (kt + 1) * 32 * ldb;
#pragma unroll
            for (int i = 0; i < 2; i++) {
                int idx = tid + i * GTHR; int kk = idx >> 4, cc = idx & 15;
                pa[i] = *(const float4*)&An[kk * B_ + m0 + 4 * cc];
            }
            {
                int kk = tid >> 3, cc = tid & 7;
                pb = *(const float4*)&Bn[kk * ldb + n0 + 4 * cc];
            }
        }
#pragma unroll
        for (int k = 0; k < 32; k++) {
            float4 av = *(const float4*)&sA[k * 68 + 4 * tm];
            float2 bv = *(const float2*)&sB[k * 36 + 2 * tn];
            c0.x = fmaf(av.x, bv.x, c0.x);
            c0.y = fmaf(av.y, bv.x, c0.y);
            c0.z = fmaf(av.z, bv.x, c0.z);
            c0.w = fmaf(av.w, bv.x, c0.w);
            c1.x = fmaf(av.x, bv.y, c1.x);
            c1.y = fmaf(av.y, bv.y, c1.y);
            c1.z = fmaf(av.z, bv.y, c1.z);
            c1.w = fmaf(av.w, bv.y, c1.w);
        }
    }
}

// ---- phase A: xh^T = (x @ Wx^T + bx)^T ; h1 = relu(xh + bh) ----------------
__global__ void __launch_bounds__(GTHR, 1) phaseA_kernel(
    const float* __restrict__ bx, const float* __restrict__ bh)
{
    float4 c0, c1;
    const int cta = blockIdx.x;
    const int m0 = (cta & 7) * 64, n0 = (cta >> 3) * 32;
    gemm_tile(g_xT, g_WxT, H_, DI_ / 32, m0, n0, c0, c1);

    const int tid = threadIdx.x;
    const int gm = m0 + 4 * (tid & 15);
    const int nA = n0 + 2 * (tid >> 4);

#pragma unroll
    for (int e = 0; e < 2; e++) {
        int n = nA + e;
        float4 c = e ? c1 : c0;
        float bxv = bx[n], bhv = bh[n];
        float4 v, h;
        v.x = c.x + bxv; v.y = c.y + bxv; v.z = c.z + bxv; v.w = c.w + bxv;
        *(float4*)&g_xh[n * B_ + gm] = v;
        h.x = fmaxf(v.x + bhv, 0.f); h.y = fmaxf(v.y + bhv, 0.f);
        h.z = fmaxf(v.z + bhv, 0.f); h.w = fmaxf(v.w + bhv, 0.f);
        *(float4*)&g_hbuf[0][n * B_ + gm] = h;
    }
}

// ---- one recurrent step: hbuf[cur^1] = relu(xh + hbuf[cur]@Wh^T + bh) ------
__global__ void __launch_bounds__(GTHR, 1) step_kernel(
    int cur, const float* __restrict__ bh)
{
    float4 c0, c1;
    const int cta = blockIdx.x;
    const int m0 = (cta & 7) * 64, n0 = (cta >> 3) * 32;
    gemm_tile(g_hbuf[cur], g_WhT, H_, H_ / 32, m0, n0, c0, c1);

    const int tid = threadIdx.x;
    const int gm = m0 + 4 * (tid & 15);
    const int nA = n0 + 2 * (tid >> 4);
    float* __restrict__ dst = g_hbuf[cur ^ 1];

#pragma unroll
    for (int e = 0; e < 2; e++) {
        int n = nA + e;
        float4 c = e ? c1 : c0;
        float bhv = bh[n];
        float4 xv = *(const float4*)&g_xh[n * B_ + gm];
        float4 h;
        h.x = fmaxf(c.x + xv.x + bhv, 0.f);
        h.y = fmaxf(c.y + xv.y + bhv, 0.f);
        h.z = fmaxf(c.z + xv.z + bhv, 0.f);
        h.w = fmaxf(c.w + xv.w + bhv, 0.f);
        *(float4*)&dst[n * B_ + gm] = h;
    }
}

// ---- output: out = h_final @ Wy^T + by  (h_final in g_hbuf[1]) -------------
__global__ void __launch_bounds__(GTHR, 1) out_kernel(
    const float* __restrict__ by, float* __restrict__ out)
{
    float4 c0, c1;
    const int cta = blockIdx.x;                 // 64 CTAs: 8 m x 8 n tiles
    const int m0 = (cta & 7) * 64, n0 = (cta >> 3) * 32;
    gemm_tile(g_hbuf[(TSTEPS - 1) & 1], g_WyT, DO_, H_ / 32, m0, n0, c0, c1);

    const int tid = threadIdx.x;
    const int gm = m0 + 4 * (tid & 15);
    const int nA = n0 + 2 * (tid >> 4);
    float bA = by[nA], bB = by[nA + 1];

    // out is [b][o] row-major: per m row store 2 adjacent n values (8B aligned)
    *(float2*)&out[(gm + 0) * DO_ + nA] = make_float2(c0.x + bA, c1.x + bB);
    *(float2*)&out[(gm + 1) * DO_ + nA] = make_float2(c0.y + bA, c1.y + bB);
    *(float2*)&out[(gm + 2) * DO_ + nA] = make_float2(c0.z + bA, c1.z + bB);
    *(float2*)&out[(gm + 3) * DO_ + nA] = make_float2(c0.w + bA, c1.w + bB);
}

// ---------------------------------------------------------------------------
extern "C" void kernel_launch(void* const* d_in, const int* in_sizes, int n_in,
                              void* d_out, int out_size)
{
    const float* x  = (const float*)d_in[0];  // [512,128]
    const float* Wx = (const float*)d_in[1];  // [512,128]
    const float* bx = (const float*)d_in[2];  // [512]
    const float* Wh = (const float*)d_in[3];  // [512,512]
    const float* bh = (const float*)d_in[4];  // [512]
    const float* Wy = (const float*)d_in[5];  // [256,512]
    const float* by = (const float*)d_in[6];  // [256]
    float* out = (float*)d_out;               // [512,256]

    transpose_kernel<<<128, TTHR>>>(x, Wx, Wh, Wy);
    phaseA_kernel<<<128, GTHR>>>(bx, bh);              // h1 in g_hbuf[0]
    for (int t = 1; t < TSTEPS; t++)
        step_kernel<<<128, GTHR>>>((t - 1) & 1, bh);   // final h in g_hbuf[1]
    out_kernel<<<64, GTHR>>>(by, out);
}